// round 11
// baseline (speedup 1.0000x reference)
#include <cuda_runtime.h>
#include <cuda_fp16.h>
#include <cstdint>
#include <cstddef>

#define CC 64
#define KK 9
#define TM 128
#define NMAX 131072
#define NTILES (NMAX/TM)
#define LEAK 0.33f

// SMEM: Wf fragments 147456 | A 4x16KB ring 65536 | idx 4608 | ss 4608
#define SM_WF  0
#define SM_A   147456
#define SM_IDX 212992
#define SM_SS  217600
#define SMEM_TOTAL 222208

// per-layer weight fragment image in u32: 9k*4kc*8nt*32lane*4(u32: bh0,bh1,bl0,bl1)
#define WF_LAYER 36864

__device__ float g_T[(size_t)NMAX*CC];
__device__ float g_Y[(size_t)NMAX*CC];
__device__ float g_X[(size_t)NMAX*CC];
__device__ __half g_Ah[(size_t)NMAX*CC];
__device__ __half g_Bh[(size_t)NMAX*CC];
__device__ unsigned g_Wf[(size_t)8*WF_LAYER];
__device__ float g_part[(size_t)NTILES*128];
__device__ float g_scale[CC];
__device__ float g_shift[CC];
__device__ int   g_mask_mode;

__device__ __forceinline__ void cpa16(unsigned d,const void* s,int ss){
    asm volatile("cp.async.cg.shared.global [%0], [%1], 16, %2;"::"r"(d),"l"(s),"r"(ss):"memory");
}
#define CP_COMMIT() asm volatile("cp.async.commit_group;":::"memory")
#define CP_WAIT(n)  asm volatile("cp.async.wait_group %0;"::"n"(n):"memory")
#define LDM4(a0,a1,a2,a3,ad) asm volatile( \
    "ldmatrix.sync.aligned.m8n8.x4.shared.b16 {%0,%1,%2,%3}, [%4];" \
    :"=r"(a0),"=r"(a1),"=r"(a2),"=r"(a3):"r"(ad))
#define LDS128(b0,b1,b2,b3,ad) asm volatile( \
    "ld.shared.v4.u32 {%0,%1,%2,%3}, [%4];":"=r"(b0),"=r"(b1),"=r"(b2),"=r"(b3):"r"(ad))
#define MMA(c,A0,A1,A2,A3,B0,B1) asm volatile( \
    "mma.sync.aligned.m16n8k16.row.col.f32.f16.f16.f32 " \
    "{%0,%1,%2,%3},{%4,%5,%6,%7},{%8,%9},{%0,%1,%2,%3};" \
    :"+f"((c)[0]),"+f"((c)[1]),"+f"((c)[2]),"+f"((c)[3]) \
    :"r"(A0),"r"(A1),"r"(A2),"r"(A3),"r"(B0),"r"(B1))

__device__ __forceinline__ unsigned short h2u(__half h){
    union{__half h; unsigned short u;} c; c.h=h; return c.u;
}

__global__ void detect_kernel(const unsigned* __restrict__ m){
    if(threadIdx.x==0&&blockIdx.x==0){
        int f32ok=1; unsigned up=0;
        for(int i=0;i<256;i++){unsigned w=m[i]; if(w!=0u&&w!=0x3F800000u)f32ok=0; up|=(w&0xFFFFFF00u);}
        g_mask_mode = f32ok?2:(up?0:1);
    }
}

// Pack fp32 W[b][k][c][d] into mma B-fragment layout, fp16 hi/lo adjacent:
// u32[4] = {bh0,bh1,bl0,bl1} per (k,kc,nt,lane).
// bh0: Wh[c0][d],Wh[c0+1][d]; bh1: Wh[c0+8][d],Wh[c0+9][d]; c0=kc*16+(lane%4)*2, d=nt*8+lane/4
__global__ void wprep_kernel(const float* __restrict__ w1,const float* __restrict__ w2,int total){
    int i=blockIdx.x*blockDim.x+threadIdx.x; if(i>=total)return;   // i over (L,k,kc,nt,lane)
    const int lane=i&31, nt=(i>>5)&7, kc=(i>>8)&3;
    const int t=i>>10, slice=t%9, L=t/9;
    const int c0=kc*16+(lane&3)*2, d=nt*8+(lane>>2);
    const float* src=(L&1)?w2:w1;
    const float* S=src+((size_t)(L>>1)*9+slice)*4096;
    unsigned r[4];
    #pragma unroll
    for(int j=0;j<2;j++){
        const int c=c0+j*8;
        float f0=S[c*64+d], f1=S[(c+1)*64+d];
        __half h0=__float2half_rn(f0), h1=__float2half_rn(f1);
        __half l0=__float2half_rn(f0-__half2float(h0));
        __half l1=__float2half_rn(f1-__half2float(h1));
        r[j]  =((unsigned)h2u(h1)<<16)|h2u(h0);
        r[2+j]=((unsigned)h2u(l1)<<16)|h2u(l0);
    }
    *(uint4*)&g_Wf[(size_t)i*4]=make_uint4(r[0],r[1],r[2],r[3]);
}

__global__ void __launch_bounds__(512,1) conv_kernel(
    const __half* __restrict__ xh,
    const unsigned* __restrict__ wf,const int* __restrict__ nidx,
    const void* __restrict__ nmask,float* __restrict__ out,
    float* __restrict__ partials,int ntiles)
{
    extern __shared__ __align__(16) char smem[];
    const unsigned sb=(unsigned)__cvta_generic_to_shared(smem);
    const int tid=threadIdx.x;
    int* idx_s=(int*)(smem+SM_IDX);
    int* ss_s =(int*)(smem+SM_SS);
    float* Ys =(float*)(smem+SM_A);          // epilogue scratch = bufs 0-1 (32KB)
    float* Sc =(float*)(smem+SM_SS);

    for(int i=tid;i<9216;i+=512)
        cpa16(sb+SM_WF+(unsigned)(i*16), (const char*)wf+(size_t)i*16, 16);
    CP_COMMIT(); CP_WAIT(0);
    __syncthreads();

    // staging: 4 threads per row, chunks 2q,2q+1 of the 128B fp16 row
    const int sr=tid>>2, q=tid&3, rsw=sr&7;
    // compute: warp w -> rows (w&7)*16, nt quad (w>>3)*4
    const int w=tid>>5, lane=tid&31;
    const int rw=w&7, nth=(w>>3)<<2;
    const int rowbase=rw<<4;
    const int rq=rowbase+(lane&15);
    const unsigned rbs=(unsigned)(rq*128);
    const int rx=rq&7, chsel=lane>>4;

    for(int t=blockIdx.x;t<ntiles;t+=gridDim.x){
        const int tile0=t*TM;
        {
            const int mode=g_mask_mode; const long gb=(long)tile0*KK;
            for(int i=tid;i<TM*KK;i+=512){
                idx_s[i]=nidx[gb+i];
                int mv;
                if(mode==0)      mv=((const unsigned char*)nmask)[gb+i];
                else if(mode==1) mv=((const int*)nmask)[gb+i]!=0;
                else             mv=((const float*)nmask)[gb+i]!=0.0f;
                ss_s[i]=mv?16:0;
            }
        }
        __syncthreads();
        // prologue: stage slices 0,1 into bufs 0,1 (separate commit groups)
        #pragma unroll
        for(int p=0;p<2;p++){
            const int id=idx_s[sr*KK+p], ss=ss_s[sr*KK+p];
            const char* s=(const char*)(xh+(size_t)id*CC);
            const unsigned db=sb+SM_A+(unsigned)(p*16384+sr*128);
            #pragma unroll
            for(int j=0;j<2;j++){
                const int ch=q*2+j;
                cpa16(db+(unsigned)((ch^rsw)<<4), s+ch*16, ss);
            }
            CP_COMMIT();
        }

        float acc[16];
        #pragma unroll
        for(int i=0;i<16;i++) acc[i]=0.0f;

        for(int k=0;k<KK;k++){
            if(k+2<KK){
                const int id=idx_s[sr*KK+k+2], ss=ss_s[sr*KK+k+2];
                const char* s=(const char*)(xh+(size_t)id*CC);
                const unsigned db=sb+SM_A+(unsigned)((((k+2)&3)*16384)+sr*128);
                #pragma unroll
                for(int j=0;j<2;j++){
                    const int ch=q*2+j;
                    cpa16(db+(unsigned)((ch^rsw)<<4), s+ch*16, ss);
                }
                CP_COMMIT(); CP_WAIT(2);
            } else { CP_WAIT(0); }
            __syncthreads();   // single barrier per slice

            const unsigned Ab=sb+SM_A+(unsigned)((k&3)*16384);
            #pragma unroll
            for(int kc=0;kc<4;kc++){
                const unsigned ch=(unsigned)((kc<<1)+chsel);
                const unsigned ah=Ab+rbs+((ch^(unsigned)rx)<<4);
                unsigned a0,a1,a2,a3;
                LDM4(a0,a1,a2,a3,ah);
                const unsigned wb=sb+SM_WF+(unsigned)(((k*4+kc)*8)*512+lane*16);
                #pragma unroll
                for(int j=0;j<4;j++){
                    const int nt=nth+j;
                    unsigned b0,b1,b2,b3;
                    LDS128(b0,b1,b2,b3,wb+(unsigned)(nt*512));
                    MMA(acc+j*4,a0,a1,a2,a3,b0,b1);
                    MMA(acc+j*4,a0,a1,a2,a3,b2,b3);
                }
            }
        }
        __syncthreads();   // all MMA reads done before Ys overwrites bufs 0-1

        {
            const int row0=rowbase+(lane>>2), row1=row0+8;
            #pragma unroll
            for(int j=0;j<4;j++){
                const int c=(nth+j)*8+(lane&3)*2;
                const int c4=c>>2, ci=c&3;
                *(float2*)(Ys+row0*64+(((c4^(row0&7))<<2)|ci))=make_float2(acc[j*4],acc[j*4+1]);
                *(float2*)(Ys+row1*64+(((c4^(row1&7))<<2)|ci))=make_float2(acc[j*4+2],acc[j*4+3]);
            }
        }
        __syncthreads();
        if(tid<256){
            const int c=tid&63; const bool sq=(tid>>6)&1; const int h=tid>>7;
            const int c4=c>>2, ci=c&3;
            float a=0.0f;
            for(int r=h*64;r<h*64+64;r++){
                float v=Ys[r*64+(((c4^(r&7))<<2)|ci)];
                a += sq ? v*v : v;
            }
            Sc[tid]=a;
        } else {
            const int lt=tid-256;
            float* og=out+(size_t)tile0*CC;
            for(int i=lt;i<2048;i+=256){
                const int r=i>>4, c4=i&15;
                *(float4*)(og+i*4)=*(float4*)(Ys+r*64+((c4^(r&7))<<2));
            }
        }
        __syncthreads();
        if(tid<128) partials[(size_t)t*128+tid]=Sc[tid]+Sc[tid+128];
        __syncthreads();
    }
}

__global__ void __launch_bounds__(1024) reduce_kernel(
    const float* __restrict__ partials,int nct,
    const float* __restrict__ gamma,const float* __restrict__ beta,float invN)
{
    __shared__ float red[1024];
    const int tid=threadIdx.x;
    const int c=tid&63, which=(tid>>6)&1, part=tid>>7;   // part 0..7
    float a=0.0f;
    for(int cta=part;cta<nct;cta+=8) a+=partials[(size_t)cta*128+which*64+c];
    red[tid]=a; __syncthreads();
    if(tid<512) red[tid]+=red[tid+512];
    __syncthreads();
    if(tid<256) red[tid]+=red[tid+256];
    __syncthreads();
    if(tid<128) red[tid]+=red[tid+128];
    __syncthreads();
    if(tid<64){
        float mean=red[tid]*invN;
        float var=red[tid+64]*invN-mean*mean;
        float sc=gamma[tid]*rsqrtf(var+1e-5f);
        g_scale[tid]=sc; g_shift[tid]=beta[tid]-mean*sc;
    }
}

__device__ __forceinline__ void hstore(__half* hp,size_t i4,float4 z){
    __half2 a=__floats2half2_rn(z.x,z.y);
    __half2 b=__floats2half2_rn(z.z,z.w);
    union{__half2 h[2]; uint2 u;} U; U.h[0]=a; U.h[1]=b;
    *(uint2*)(hp+i4*4)=U.u;
}

__global__ void __launch_bounds__(256) convert_kernel(
    const float* __restrict__ x,__half* hp,int n4){
    int i=blockIdx.x*blockDim.x+threadIdx.x; if(i>=n4)return;
    hstore(hp,(size_t)i,((const float4*)x)[i]);
}

__global__ void __launch_bounds__(256) bnleaky_kernel(
    const float* __restrict__ t,__half* hp,int n4){
    int i=blockIdx.x*blockDim.x+threadIdx.x; if(i>=n4)return;
    const int c=(i<<2)&63;
    const float4 sc=*(const float4*)(g_scale+c), sh=*(const float4*)(g_shift+c);
    float4 v=((const float4*)t)[i]; float x;
    x=v.x*sc.x+sh.x; v.x=x>0?x:LEAK*x;
    x=v.y*sc.y+sh.y; v.y=x>0?x:LEAK*x;
    x=v.z*sc.z+sh.z; v.z=x>0?x:LEAK*x;
    x=v.w*sc.w+sh.w; v.w=x>0?x:LEAK*x;
    hstore(hp,(size_t)i,v);
}

__global__ void __launch_bounds__(256) bnresleaky_kernel(
    const float* __restrict__ y,const float* __restrict__ res,float* __restrict__ op,
    __half* hp,int wp,int n4){
    int i=blockIdx.x*blockDim.x+threadIdx.x; if(i>=n4)return;
    const int c=(i<<2)&63;
    const float4 sc=*(const float4*)(g_scale+c), sh=*(const float4*)(g_shift+c);
    float4 v=((const float4*)y)[i]; const float4 r=((const float4*)res)[i]; float x;
    x=v.x*sc.x+sh.x+r.x; v.x=x>0?x:LEAK*x;
    x=v.y*sc.y+sh.y+r.y; v.y=x>0?x:LEAK*x;
    x=v.z*sc.z+sh.z+r.z; v.z=x>0?x:LEAK*x;
    x=v.w*sc.w+sh.w+r.w; v.w=x>0?x:LEAK*x;
    ((float4*)op)[i]=v;
    if(wp) hstore(hp,(size_t)i,v);
}

extern "C" void kernel_launch(void* const* d_in,const int* in_sizes,int n_in,
                              void* d_out,int out_size)
{
    const float* features=(const float*)d_in[0];
    const int*   nidx    =(const int*)d_in[1];
    const void*  nmask   =d_in[2];
    const float* conv1w  =(const float*)d_in[3];
    const float* bn1g    =(const float*)d_in[4];
    const float* bn1b    =(const float*)d_in[5];
    const float* conv2w  =(const float*)d_in[6];
    const float* bn2g    =(const float*)d_in[7];
    const float* bn2b    =(const float*)d_in[8];
    float* out=(float*)d_out;

    const int N=in_sizes[0]/CC, nct=N/TM, n4=(N*CC)/4;
    const float invN=1.0f/(float)N;
    const int B=in_sizes[3]/(KK*CC*CC);

    float *pT,*pY,*pX,*pPart; __half *pAh,*pBh; unsigned* pW;
    cudaGetSymbolAddress((void**)&pT,g_T);
    cudaGetSymbolAddress((void**)&pY,g_Y);
    cudaGetSymbolAddress((void**)&pX,g_X);
    cudaGetSymbolAddress((void**)&pPart,g_part);
    cudaGetSymbolAddress((void**)&pAh,g_Ah);
    cudaGetSymbolAddress((void**)&pBh,g_Bh);
    cudaGetSymbolAddress((void**)&pW,g_Wf);

    cudaFuncSetAttribute(conv_kernel,cudaFuncAttributeMaxDynamicSharedMemorySize,SMEM_TOTAL);

    detect_kernel<<<1,1>>>((const unsigned*)nmask);
    wprep_kernel<<<(B*2*9216+255)/256,256>>>(conv1w,conv2w,B*2*9216);
    convert_kernel<<<(n4+255)/256,256>>>(features,pAh,n4);

    const float* xcur=features;
    for(int b=0;b<B;b++){
        conv_kernel<<<148,512,SMEM_TOTAL>>>(pAh,pW+(size_t)(b*2)*WF_LAYER,nidx,nmask,pT,pPart,nct);
        reduce_kernel<<<1,1024>>>(pPart,nct,bn1g+b*CC,bn1b+b*CC,invN);
        bnleaky_kernel<<<(n4+255)/256,256>>>(pT,pBh,n4);

        conv_kernel<<<148,512,SMEM_TOTAL>>>(pBh,pW+(size_t)(b*2+1)*WF_LAYER,nidx,nmask,pY,pPart,nct);
        reduce_kernel<<<1,1024>>>(pPart,nct,bn2g+b*CC,bn2b+b*CC,invN);

        float* dst=(b==B-1)?out:pX;
        bnresleaky_kernel<<<(n4+255)/256,256>>>(pY,xcur,dst,pAh,b<B-1,n4);
        xcur=dst;
    }
}

// round 12
// speedup vs baseline: 1.0722x; 1.0722x over previous
#include <cuda_runtime.h>
#include <cuda_fp16.h>
#include <cstdint>
#include <cstddef>

#define CC 64
#define KK 9
#define TM 128
#define NMAX 131072
#define NTILES (NMAX/TM)
#define LEAK 0.33f

// SMEM: Wf fragments 147456 | A 4x16KB ring 65536 | idx 4608 | ss 4608
#define SM_WF  0
#define SM_A   147456
#define SM_IDX 212992
#define SM_SS  217600
#define SMEM_TOTAL 222208

// per-layer weight fragment image in u32: 9k*4kc*8nt*32lane*4(u32: bh0,bh1,bl0,bl1)
#define WF_LAYER 36864

__device__ float g_T[(size_t)NMAX*CC];
__device__ float g_Y[(size_t)NMAX*CC];
__device__ float g_X[(size_t)NMAX*CC];
__device__ __half g_Ah[(size_t)NMAX*CC];
__device__ __half g_Bh[(size_t)NMAX*CC];
__device__ unsigned g_Wf[(size_t)8*WF_LAYER];
__device__ float g_part[(size_t)NTILES*128];
__device__ float g_scale[CC];
__device__ float g_shift[CC];
__device__ int   g_mask_mode;

__device__ __forceinline__ void cpa16(unsigned d,const void* s,int ss){
    asm volatile("cp.async.cg.shared.global [%0], [%1], 16, %2;"::"r"(d),"l"(s),"r"(ss):"memory");
}
#define CP_COMMIT() asm volatile("cp.async.commit_group;":::"memory")
#define CP_WAIT(n)  asm volatile("cp.async.wait_group %0;"::"n"(n):"memory")
#define LDM4(a0,a1,a2,a3,ad) asm volatile( \
    "ldmatrix.sync.aligned.m8n8.x4.shared.b16 {%0,%1,%2,%3}, [%4];" \
    :"=r"(a0),"=r"(a1),"=r"(a2),"=r"(a3):"r"(ad))
#define LDS128(b0,b1,b2,b3,ad) asm volatile( \
    "ld.shared.v4.u32 {%0,%1,%2,%3}, [%4];":"=r"(b0),"=r"(b1),"=r"(b2),"=r"(b3):"r"(ad))
#define MMA(c,A0,A1,A2,A3,B0,B1) asm volatile( \
    "mma.sync.aligned.m16n8k16.row.col.f32.f16.f16.f32 " \
    "{%0,%1,%2,%3},{%4,%5,%6,%7},{%8,%9},{%0,%1,%2,%3};" \
    :"+f"((c)[0]),"+f"((c)[1]),"+f"((c)[2]),"+f"((c)[3]) \
    :"r"(A0),"r"(A1),"r"(A2),"r"(A3),"r"(B0),"r"(B1))

__device__ __forceinline__ unsigned short h2u(__half h){
    union{__half h; unsigned short u;} c; c.h=h; return c.u;
}

__global__ void detect_kernel(const unsigned* __restrict__ m){
    if(threadIdx.x==0&&blockIdx.x==0){
        int f32ok=1; unsigned up=0;
        for(int i=0;i<256;i++){unsigned w=m[i]; if(w!=0u&&w!=0x3F800000u)f32ok=0; up|=(w&0xFFFFFF00u);}
        g_mask_mode = f32ok?2:(up?0:1);
    }
}

// Pack fp32 W[b][k][c][d] into mma B-fragment layout, fp16 hi/lo adjacent.
__global__ void wprep_kernel(const float* __restrict__ w1,const float* __restrict__ w2,int total){
    int i=blockIdx.x*blockDim.x+threadIdx.x; if(i>=total)return;   // i over (L,k,kc,nt,lane)
    const int lane=i&31, nt=(i>>5)&7, kc=(i>>8)&3;
    const int t=i>>10, slice=t%9, L=t/9;
    const int c0=kc*16+(lane&3)*2, d=nt*8+(lane>>2);
    const float* src=(L&1)?w2:w1;
    const float* S=src+((size_t)(L>>1)*9+slice)*4096;
    unsigned r[4];
    #pragma unroll
    for(int j=0;j<2;j++){
        const int c=c0+j*8;
        float f0=S[c*64+d], f1=S[(c+1)*64+d];
        __half h0=__float2half_rn(f0), h1=__float2half_rn(f1);
        __half l0=__float2half_rn(f0-__half2float(h0));
        __half l1=__float2half_rn(f1-__half2float(h1));
        r[j]  =((unsigned)h2u(h1)<<16)|h2u(h0);
        r[2+j]=((unsigned)h2u(l1)<<16)|h2u(l0);
    }
    *(uint4*)&g_Wf[(size_t)i*4]=make_uint4(r[0],r[1],r[2],r[3]);
}

__global__ void __launch_bounds__(512,1) conv_kernel(
    const __half* __restrict__ xh,
    const unsigned* __restrict__ wf,const int* __restrict__ nidx,
    const void* __restrict__ nmask,float* __restrict__ out,
    float* __restrict__ partials,int ntiles)
{
    extern __shared__ __align__(16) char smem[];
    const unsigned sb=(unsigned)__cvta_generic_to_shared(smem);
    const int tid=threadIdx.x;
    int* idx_s=(int*)(smem+SM_IDX);
    int* ss_s =(int*)(smem+SM_SS);
    float* Ys =(float*)(smem+SM_A);          // epilogue scratch = bufs 0-1 (32KB)
    float* Sc =(float*)(smem+SM_SS);

    for(int i=tid;i<9216;i+=512)
        cpa16(sb+SM_WF+(unsigned)(i*16), (const char*)wf+(size_t)i*16, 16);
    CP_COMMIT(); CP_WAIT(0);
    __syncthreads();

    // staging: 4 threads per row, chunks 2q,2q+1 of the 128B fp16 row
    const int sr=tid>>2, q=tid&3, rsw=sr&7;
    // compute: warp w -> row group (w&3)*32 (2 m16 tiles), nt pair (w>>2)*2
    const int w=tid>>5, lane=tid&31;
    const int rw=w&3, ntg=w>>2;
    const int rowbase=rw<<5;
    const int rq0=rowbase+(lane&15), rq1=rq0+16;
    const unsigned rbs0=(unsigned)(rq0*128), rbs1=(unsigned)(rq1*128);
    const int rx=rq0&7, chsel=lane>>4;   // rq1&7 == rq0&7

    for(int t=blockIdx.x;t<ntiles;t+=gridDim.x){
        const int tile0=t*TM;
        {
            const int mode=g_mask_mode; const long gb=(long)tile0*KK;
            for(int i=tid;i<TM*KK;i+=512){
                idx_s[i]=nidx[gb+i];
                int mv;
                if(mode==0)      mv=((const unsigned char*)nmask)[gb+i];
                else if(mode==1) mv=((const int*)nmask)[gb+i]!=0;
                else             mv=((const float*)nmask)[gb+i]!=0.0f;
                ss_s[i]=mv?16:0;
            }
        }
        __syncthreads();
        // prologue: stage slices 0,1 into bufs 0,1 (separate commit groups)
        #pragma unroll
        for(int p=0;p<2;p++){
            const int id=idx_s[sr*KK+p], ss=ss_s[sr*KK+p];
            const char* s=(const char*)(xh+(size_t)id*CC);
            const unsigned db=sb+SM_A+(unsigned)(p*16384+sr*128);
            #pragma unroll
            for(int j=0;j<2;j++){
                const int ch=q*2+j;
                cpa16(db+(unsigned)((ch^rsw)<<4), s+ch*16, ss);
            }
            CP_COMMIT();
        }

        float acc[16];   // [rt0: nt0 x4, nt1 x4 | rt1: nt0 x4, nt1 x4]
        #pragma unroll
        for(int i=0;i<16;i++) acc[i]=0.0f;

        for(int k=0;k<KK;k++){
            if(k+2<KK){
                const int id=idx_s[sr*KK+k+2], ss=ss_s[sr*KK+k+2];
                const char* s=(const char*)(xh+(size_t)id*CC);
                const unsigned db=sb+SM_A+(unsigned)((((k+2)&3)*16384)+sr*128);
                #pragma unroll
                for(int j=0;j<2;j++){
                    const int ch=q*2+j;
                    cpa16(db+(unsigned)((ch^rsw)<<4), s+ch*16, ss);
                }
                CP_COMMIT(); CP_WAIT(2);
            } else { CP_WAIT(0); }
            __syncthreads();   // single barrier per slice

            const unsigned Ab=sb+SM_A+(unsigned)((k&3)*16384);
            #pragma unroll
            for(int kc=0;kc<4;kc++){
                const unsigned ch=(unsigned)((kc<<1)+chsel);
                const unsigned co=(ch^(unsigned)rx)<<4;
                unsigned a0,a1,a2,a3,a4,a5,a6,a7;
                LDM4(a0,a1,a2,a3,Ab+rbs0+co);
                LDM4(a4,a5,a6,a7,Ab+rbs1+co);
                const unsigned wb=sb+SM_WF+(unsigned)(((k*4+kc)*8)*512+lane*16);
                #pragma unroll
                for(int j=0;j<2;j++){
                    const int nt=ntg*2+j;
                    unsigned b0,b1,b2,b3;
                    LDS128(b0,b1,b2,b3,wb+(unsigned)(nt*512));
                    MMA(acc+j*4,  a0,a1,a2,a3,b0,b1);
                    MMA(acc+j*4,  a0,a1,a2,a3,b2,b3);
                    MMA(acc+8+j*4,a4,a5,a6,a7,b0,b1);
                    MMA(acc+8+j*4,a4,a5,a6,a7,b2,b3);
                }
            }
        }
        __syncthreads();   // all MMA reads done before Ys overwrites bufs 0-1

        {
            #pragma unroll
            for(int rt=0;rt<2;rt++){
                const int row0=rowbase+rt*16+(lane>>2), row1=row0+8;
                #pragma unroll
                for(int j=0;j<2;j++){
                    const int c=(ntg*2+j)*8+(lane&3)*2;
                    const int c4=c>>2, ci=c&3;
                    const float* a=acc+rt*8+j*4;
                    *(float2*)(Ys+row0*64+(((c4^(row0&7))<<2)|ci))=make_float2(a[0],a[1]);
                    *(float2*)(Ys+row1*64+(((c4^(row1&7))<<2)|ci))=make_float2(a[2],a[3]);
                }
            }
        }
        __syncthreads();
        if(tid<256){
            const int c=tid&63; const bool sq=(tid>>6)&1; const int h=tid>>7;
            const int c4=c>>2, ci=c&3;
            float a=0.0f;
            for(int r=h*64;r<h*64+64;r++){
                float v=Ys[r*64+(((c4^(r&7))<<2)|ci)];
                a += sq ? v*v : v;
            }
            Sc[tid]=a;
        } else {
            const int lt=tid-256;
            float* og=out+(size_t)tile0*CC;
            for(int i=lt;i<2048;i+=256){
                const int r=i>>4, c4=i&15;
                *(float4*)(og+i*4)=*(float4*)(Ys+r*64+((c4^(r&7))<<2));
            }
        }
        __syncthreads();
        if(tid<128) partials[(size_t)t*128+tid]=Sc[tid]+Sc[tid+128];
        __syncthreads();
    }
}

__global__ void __launch_bounds__(1024) reduce_kernel(
    const float* __restrict__ partials,int nct,
    const float* __restrict__ gamma,const float* __restrict__ beta,float invN)
{
    __shared__ float red[1024];
    const int tid=threadIdx.x;
    const int c=tid&63, which=(tid>>6)&1, part=tid>>7;   // part 0..7
    float a=0.0f;
    for(int cta=part;cta<nct;cta+=8) a+=partials[(size_t)cta*128+which*64+c];
    red[tid]=a; __syncthreads();
    if(tid<512) red[tid]+=red[tid+512];
    __syncthreads();
    if(tid<256) red[tid]+=red[tid+256];
    __syncthreads();
    if(tid<128) red[tid]+=red[tid+128];
    __syncthreads();
    if(tid<64){
        float mean=red[tid]*invN;
        float var=red[tid+64]*invN-mean*mean;
        float sc=gamma[tid]*rsqrtf(var+1e-5f);
        g_scale[tid]=sc; g_shift[tid]=beta[tid]-mean*sc;
    }
}

__device__ __forceinline__ void hstore(__half* hp,size_t i4,float4 z){
    __half2 a=__floats2half2_rn(z.x,z.y);
    __half2 b=__floats2half2_rn(z.z,z.w);
    union{__half2 h[2]; uint2 u;} U; U.h[0]=a; U.h[1]=b;
    *(uint2*)(hp+i4*4)=U.u;
}

__global__ void __launch_bounds__(256) convert_kernel(
    const float* __restrict__ x,__half* hp,int n4){
    int i=blockIdx.x*blockDim.x+threadIdx.x; if(i>=n4)return;
    hstore(hp,(size_t)i,((const float4*)x)[i]);
}

__global__ void __launch_bounds__(256) bnleaky_kernel(
    const float* __restrict__ t,__half* hp,int n4){
    int i=blockIdx.x*blockDim.x+threadIdx.x; if(i>=n4)return;
    const int c=(i<<2)&63;
    const float4 sc=*(const float4*)(g_scale+c), sh=*(const float4*)(g_shift+c);
    float4 v=((const float4*)t)[i]; float x;
    x=v.x*sc.x+sh.x; v.x=x>0?x:LEAK*x;
    x=v.y*sc.y+sh.y; v.y=x>0?x:LEAK*x;
    x=v.z*sc.z+sh.z; v.z=x>0?x:LEAK*x;
    x=v.w*sc.w+sh.w; v.w=x>0?x:LEAK*x;
    hstore(hp,(size_t)i,v);
}

__global__ void __launch_bounds__(256) bnresleaky_kernel(
    const float* __restrict__ y,const float* __restrict__ res,float* __restrict__ op,
    __half* hp,int wp,int n4){
    int i=blockIdx.x*blockDim.x+threadIdx.x; if(i>=n4)return;
    const int c=(i<<2)&63;
    const float4 sc=*(const float4*)(g_scale+c), sh=*(const float4*)(g_shift+c);
    float4 v=((const float4*)y)[i]; const float4 r=((const float4*)res)[i]; float x;
    x=v.x*sc.x+sh.x+r.x; v.x=x>0?x:LEAK*x;
    x=v.y*sc.y+sh.y+r.y; v.y=x>0?x:LEAK*x;
    x=v.z*sc.z+sh.z+r.z; v.z=x>0?x:LEAK*x;
    x=v.w*sc.w+sh.w+r.w; v.w=x>0?x:LEAK*x;
    ((float4*)op)[i]=v;
    if(wp) hstore(hp,(size_t)i,v);
}

extern "C" void kernel_launch(void* const* d_in,const int* in_sizes,int n_in,
                              void* d_out,int out_size)
{
    const float* features=(const float*)d_in[0];
    const int*   nidx    =(const int*)d_in[1];
    const void*  nmask   =d_in[2];
    const float* conv1w  =(const float*)d_in[3];
    const float* bn1g    =(const float*)d_in[4];
    const float* bn1b    =(const float*)d_in[5];
    const float* conv2w  =(const float*)d_in[6];
    const float* bn2g    =(const float*)d_in[7];
    const float* bn2b    =(const float*)d_in[8];
    float* out=(float*)d_out;

    const int N=in_sizes[0]/CC, nct=N/TM, n4=(N*CC)/4;
    const float invN=1.0f/(float)N;
    const int B=in_sizes[3]/(KK*CC*CC);

    float *pT,*pY,*pX,*pPart; __half *pAh,*pBh; unsigned* pW;
    cudaGetSymbolAddress((void**)&pT,g_T);
    cudaGetSymbolAddress((void**)&pY,g_Y);
    cudaGetSymbolAddress((void**)&pX,g_X);
    cudaGetSymbolAddress((void**)&pPart,g_part);
    cudaGetSymbolAddress((void**)&pAh,g_Ah);
    cudaGetSymbolAddress((void**)&pBh,g_Bh);
    cudaGetSymbolAddress((void**)&pW,g_Wf);

    cudaFuncSetAttribute(conv_kernel,cudaFuncAttributeMaxDynamicSharedMemorySize,SMEM_TOTAL);

    detect_kernel<<<1,1>>>((const unsigned*)nmask);
    wprep_kernel<<<(B*2*9216+255)/256,256>>>(conv1w,conv2w,B*2*9216);
    convert_kernel<<<(n4+255)/256,256>>>(features,pAh,n4);

    const float* xcur=features;
    for(int b=0;b<B;b++){
        conv_kernel<<<148,512,SMEM_TOTAL>>>(pAh,pW+(size_t)(b*2)*WF_LAYER,nidx,nmask,pT,pPart,nct);
        reduce_kernel<<<1,1024>>>(pPart,nct,bn1g+b*CC,bn1b+b*CC,invN);
        bnleaky_kernel<<<(n4+255)/256,256>>>(pT,pBh,n4);

        conv_kernel<<<148,512,SMEM_TOTAL>>>(pBh,pW+(size_t)(b*2+1)*WF_LAYER,nidx,nmask,pY,pPart,nct);
        reduce_kernel<<<1,1024>>>(pPart,nct,bn2g+b*CC,bn2b+b*CC,invN);

        float* dst=(b==B-1)?out:pX;
        bnresleaky_kernel<<<(n4+255)/256,256>>>(pY,xcur,dst,pAh,b<B-1,n4);
        xcur=dst;
    }
}

// round 13
// speedup vs baseline: 1.2951x; 1.2079x over previous
#include <cuda_runtime.h>
#include <cuda_fp16.h>
#include <cstdint>
#include <cstddef>

#define CC 64
#define KK 9
#define TM 128
#define NMAX 131072
#define NTILES (NMAX/TM)
#define LEAK 0.33f

// SMEM: Wf 73728 | A ring 4x16KB 65536 | idx(packed mask) 4608 | Sc 2048
#define SM_WF  0
#define SM_A   73728
#define SM_IDX 139264
#define SM_SC  143872
#define SMEM_TOTAL 145920

// per-layer weight fragment image in u32: 9k*4kc*4ntp*32lane*4(u32: nt0b0,nt0b1,nt1b0,nt1b1)
#define WF_LAYER 18432

__device__ float g_T[(size_t)NMAX*CC];
__device__ float g_Y[(size_t)NMAX*CC];
__device__ float g_X[(size_t)NMAX*CC];
__device__ __half g_Ah[(size_t)NMAX*CC];
__device__ __half g_Bh[(size_t)NMAX*CC];
__device__ unsigned g_Wf[(size_t)8*WF_LAYER];
__device__ float g_part[(size_t)NTILES*128];
__device__ float g_scale[CC];
__device__ float g_shift[CC];
__device__ int   g_mask_mode;

__device__ __forceinline__ void cpa16(unsigned d,const void* s,int ss){
    asm volatile("cp.async.cg.shared.global [%0], [%1], 16, %2;"::"r"(d),"l"(s),"r"(ss):"memory");
}
#define CP_COMMIT() asm volatile("cp.async.commit_group;":::"memory")
#define CP_WAIT(n)  asm volatile("cp.async.wait_group %0;"::"n"(n):"memory")
#define LDM4(a0,a1,a2,a3,ad) asm volatile( \
    "ldmatrix.sync.aligned.m8n8.x4.shared.b16 {%0,%1,%2,%3}, [%4];" \
    :"=r"(a0),"=r"(a1),"=r"(a2),"=r"(a3):"r"(ad))
#define LDS128(b0,b1,b2,b3,ad) asm volatile( \
    "ld.shared.v4.u32 {%0,%1,%2,%3}, [%4];":"=r"(b0),"=r"(b1),"=r"(b2),"=r"(b3):"r"(ad))
#define MMA(c,A0,A1,A2,A3,B0,B1) asm volatile( \
    "mma.sync.aligned.m16n8k16.row.col.f32.f16.f16.f32 " \
    "{%0,%1,%2,%3},{%4,%5,%6,%7},{%8,%9},{%0,%1,%2,%3};" \
    :"+f"((c)[0]),"+f"((c)[1]),"+f"((c)[2]),"+f"((c)[3]) \
    :"r"(A0),"r"(A1),"r"(A2),"r"(A3),"r"(B0),"r"(B1))

__device__ __forceinline__ unsigned short h2u(__half h){
    union{__half h; unsigned short u;} c; c.h=h; return c.u;
}

__global__ void detect_kernel(const unsigned* __restrict__ m){
    if(threadIdx.x==0&&blockIdx.x==0){
        int f32ok=1; unsigned up=0;
        for(int i=0;i<256;i++){unsigned w=m[i]; if(w!=0u&&w!=0x3F800000u)f32ok=0; up|=(w&0xFFFFFF00u);}
        g_mask_mode = f32ok?2:(up?0:1);
    }
}

// Pack fp32 W[b][k][c][d] into mma B-fragment layout, single fp16 plane.
// u32[4] per (k,kc,ntp,lane) = {nt0_b0, nt0_b1, nt1_b0, nt1_b1}, nt = ntp*2+j
__global__ void wprep_kernel(const float* __restrict__ w1,const float* __restrict__ w2,int total){
    int i=blockIdx.x*blockDim.x+threadIdx.x; if(i>=total)return;  // (L,k,kc,ntp,lane)
    const int lane=i&31, ntp=(i>>5)&3, kc=(i>>7)&3;
    const int t=i>>9, slice=t%9, L=t/9;
    const int c0=kc*16+(lane&3)*2;
    const float* src=(L&1)?w2:w1;
    const float* S=src+((size_t)(L>>1)*9+slice)*4096;
    unsigned r[4];
    #pragma unroll
    for(int j=0;j<2;j++){
        const int d=(ntp*2+j)*8+(lane>>2);
        __half h0=__float2half_rn(S[c0*64+d]);
        __half h1=__float2half_rn(S[(c0+1)*64+d]);
        __half h2=__float2half_rn(S[(c0+8)*64+d]);
        __half h3=__float2half_rn(S[(c0+9)*64+d]);
        r[2*j]  =((unsigned)h2u(h1)<<16)|h2u(h0);
        r[2*j+1]=((unsigned)h2u(h3)<<16)|h2u(h2);
    }
    *(uint4*)&g_Wf[(size_t)i*4]=make_uint4(r[0],r[1],r[2],r[3]);
}

__global__ void __launch_bounds__(512,1) conv_kernel(
    const __half* __restrict__ xh,
    const unsigned* __restrict__ wf,const int* __restrict__ nidx,
    const void* __restrict__ nmask,float* __restrict__ out,
    float* __restrict__ partials,int ntiles)
{
    extern __shared__ __align__(16) char smem[];
    const unsigned sb=(unsigned)__cvta_generic_to_shared(smem);
    const int tid=threadIdx.x;
    int* idx_s=(int*)(smem+SM_IDX);
    float* Sc =(float*)(smem+SM_SC);   // 512 floats: [sq][rw][c]

    for(int i=tid;i<4608;i+=512)
        cpa16(sb+SM_WF+(unsigned)(i*16), (const char*)wf+(size_t)i*16, 16);
    CP_COMMIT(); CP_WAIT(0);
    __syncthreads();

    // staging: 4 threads per row, chunks 2q,2q+1 of the 128B fp16 row
    const int sr=tid>>2, q=tid&3, rsw=sr&7;
    // compute: warp w -> row group (w&3)*32 (2 m16 tiles), ntp = w>>2 (cols ntp*16..+16)
    const int w=tid>>5, lane=tid&31;
    const int rw=w&3, ntg=w>>2;
    const int rowbase=rw<<5;
    const int rq0=rowbase+(lane&15), rq1=rq0+16;
    const unsigned rbs0=(unsigned)(rq0*128), rbs1=(unsigned)(rq1*128);
    const int rx=rq0&7, chsel=lane>>4;

    for(int t=blockIdx.x;t<ntiles;t+=gridDim.x){
        const int tile0=t*TM;
        {
            const int mode=g_mask_mode; const long gb=(long)tile0*KK;
            for(int i=tid;i<TM*KK;i+=512){
                int id=nidx[gb+i];
                int mv;
                if(mode==0)      mv=((const unsigned char*)nmask)[gb+i];
                else if(mode==1) mv=((const int*)nmask)[gb+i]!=0;
                else             mv=((const float*)nmask)[gb+i]!=0.0f;
                idx_s[i]= mv ? id : (id|(int)0x80000000);
            }
        }
        __syncthreads();
        // prologue: stage slices 0,1 into bufs 0,1 (separate commit groups)
        #pragma unroll
        for(int p=0;p<2;p++){
            const int v=idx_s[sr*KK+p];
            const int ss=(v>=0)?16:0;
            const char* s=(const char*)(xh+(size_t)(v&0x7FFFFFFF)*CC);
            const unsigned db=sb+SM_A+(unsigned)(p*16384+sr*128);
            #pragma unroll
            for(int j=0;j<2;j++){
                const int ch=q*2+j;
                cpa16(db+(unsigned)((ch^rsw)<<4), s+ch*16, ss);
            }
            CP_COMMIT();
        }

        float acc[16];   // [rt][nt(2)][4]
        #pragma unroll
        for(int i=0;i<16;i++) acc[i]=0.0f;

        for(int k=0;k<KK;k++){
            if(k+2<KK){
                const int v=idx_s[sr*KK+k+2];
                const int ss=(v>=0)?16:0;
                const char* s=(const char*)(xh+(size_t)(v&0x7FFFFFFF)*CC);
                const unsigned db=sb+SM_A+(unsigned)((((k+2)&3)*16384)+sr*128);
                #pragma unroll
                for(int j=0;j<2;j++){
                    const int ch=q*2+j;
                    cpa16(db+(unsigned)((ch^rsw)<<4), s+ch*16, ss);
                }
                CP_COMMIT(); CP_WAIT(2);
            } else { CP_WAIT(0); }
            __syncthreads();   // single barrier per slice

            const unsigned Ab=sb+SM_A+(unsigned)((k&3)*16384);
            #pragma unroll
            for(int kc=0;kc<4;kc++){
                const unsigned ch=(unsigned)((kc<<1)+chsel);
                const unsigned co=(ch^(unsigned)rx)<<4;
                unsigned a0,a1,a2,a3,a4,a5,a6,a7;
                LDM4(a0,a1,a2,a3,Ab+rbs0+co);
                LDM4(a4,a5,a6,a7,Ab+rbs1+co);
                unsigned b0,b1,b2,b3;
                LDS128(b0,b1,b2,b3,sb+SM_WF+(unsigned)((((k*4+kc)<<2)+ntg)*512+lane*16));
                MMA(acc+0, a0,a1,a2,a3,b0,b1);
                MMA(acc+4, a0,a1,a2,a3,b2,b3);
                MMA(acc+8, a4,a5,a6,a7,b0,b1);
                MMA(acc+12,a4,a5,a6,a7,b2,b3);
            }
        }
        __syncthreads();   // all MMA reads done before next prologue reuses bufs

        // direct-from-register output writes (32B sectors)
        {
            float* og=out+(size_t)tile0*CC;
            #pragma unroll
            for(int rt=0;rt<2;rt++){
                const int row0=rowbase+rt*16+(lane>>2), row1=row0+8;
                #pragma unroll
                for(int j=0;j<2;j++){
                    const int c=ntg*16+j*8+(lane&3)*2;
                    const float* a=acc+rt*8+j*4;
                    *(float2*)(og+(size_t)row0*CC+c)=make_float2(a[0],a[1]);
                    *(float2*)(og+(size_t)row1*CC+c)=make_float2(a[2],a[3]);
                }
            }
        }
        // per-channel BN partials via shuffle reduce (cols: j*8+(lane&3)*2+b)
        {
            float s[4], qv[4];
            #pragma unroll
            for(int j=0;j<2;j++)
                #pragma unroll
                for(int b=0;b<2;b++){
                    float a0=acc[0+j*4+b],  a1=acc[0+j*4+2+b];
                    float a2=acc[8+j*4+b],  a3=acc[8+j*4+2+b];
                    s [j*2+b]=a0+a1+a2+a3;
                    qv[j*2+b]=a0*a0+a1*a1+a2*a2+a3*a3;
                }
            #pragma unroll
            for(int m=4;m<32;m<<=1)
                #pragma unroll
                for(int i=0;i<4;i++){
                    s [i]+=__shfl_xor_sync(0xffffffffu,s [i],m);
                    qv[i]+=__shfl_xor_sync(0xffffffffu,qv[i],m);
                }
            if(lane<4){
                #pragma unroll
                for(int i=0;i<4;i++){
                    const int c=ntg*16+(i>>1)*8+lane*2+(i&1);
                    Sc[rw*64+c]    =s [i];
                    Sc[256+rw*64+c]=qv[i];
                }
            }
        }
        __syncthreads();
        if(tid<128){
            const int which=tid>>6, c=tid&63;
            const float* S0=Sc+which*256;
            partials[(size_t)t*128+tid]=S0[c]+S0[64+c]+S0[128+c]+S0[192+c];
        }
        // next-tile idx fill + its barrier provide the remaining ordering
    }
}

__global__ void __launch_bounds__(1024) reduce_kernel(
    const float* __restrict__ partials,int nct,
    const float* __restrict__ gamma,const float* __restrict__ beta,float invN)
{
    __shared__ float red[1024];
    const int tid=threadIdx.x;
    const int c=tid&63, which=(tid>>6)&1, part=tid>>7;   // part 0..7
    float a=0.0f;
    for(int cta=part;cta<nct;cta+=8) a+=partials[(size_t)cta*128+which*64+c];
    red[tid]=a; __syncthreads();
    if(tid<512) red[tid]+=red[tid+512];
    __syncthreads();
    if(tid<256) red[tid]+=red[tid+256];
    __syncthreads();
    if(tid<128) red[tid]+=red[tid+128];
    __syncthreads();
    if(tid<64){
        float mean=red[tid]*invN;
        float var=red[tid+64]*invN-mean*mean;
        float sc=gamma[tid]*rsqrtf(var+1e-5f);
        g_scale[tid]=sc; g_shift[tid]=beta[tid]-mean*sc;
    }
}

__device__ __forceinline__ void hstore(__half* hp,size_t i4,float4 z){
    __half2 a=__floats2half2_rn(z.x,z.y);
    __half2 b=__floats2half2_rn(z.z,z.w);
    union{__half2 h[2]; uint2 u;} U; U.h[0]=a; U.h[1]=b;
    *(uint2*)(hp+i4*4)=U.u;
}

__global__ void __launch_bounds__(256) convert_kernel(
    const float* __restrict__ x,__half* hp,int n4){
    int i=blockIdx.x*blockDim.x+threadIdx.x; if(i>=n4)return;
    hstore(hp,(size_t)i,((const float4*)x)[i]);
}

__global__ void __launch_bounds__(256) bnleaky_kernel(
    const float* __restrict__ t,__half* hp,int n4){
    int i=blockIdx.x*blockDim.x+threadIdx.x; if(i>=n4)return;
    const int c=(i<<2)&63;
    const float4 sc=*(const float4*)(g_scale+c), sh=*(const float4*)(g_shift+c);
    float4 v=((const float4*)t)[i]; float x;
    x=v.x*sc.x+sh.x; v.x=x>0?x:LEAK*x;
    x=v.y*sc.y+sh.y; v.y=x>0?x:LEAK*x;
    x=v.z*sc.z+sh.z; v.z=x>0?x:LEAK*x;
    x=v.w*sc.w+sh.w; v.w=x>0?x:LEAK*x;
    hstore(hp,(size_t)i,v);
}

__global__ void __launch_bounds__(256) bnresleaky_kernel(
    const float* __restrict__ y,const float* __restrict__ res,float* __restrict__ op,
    __half* hp,int wp,int n4){
    int i=blockIdx.x*blockDim.x+threadIdx.x; if(i>=n4)return;
    const int c=(i<<2)&63;
    const float4 sc=*(const float4*)(g_scale+c), sh=*(const float4*)(g_shift+c);
    float4 v=((const float4*)y)[i]; const float4 r=((const float4*)res)[i]; float x;
    x=v.x*sc.x+sh.x+r.x; v.x=x>0?x:LEAK*x;
    x=v.y*sc.y+sh.y+r.y; v.y=x>0?x:LEAK*x;
    x=v.z*sc.z+sh.z+r.z; v.z=x>0?x:LEAK*x;
    x=v.w*sc.w+sh.w+r.w; v.w=x>0?x:LEAK*x;
    ((float4*)op)[i]=v;
    if(wp) hstore(hp,(size_t)i,v);
}

extern "C" void kernel_launch(void* const* d_in,const int* in_sizes,int n_in,
                              void* d_out,int out_size)
{
    const float* features=(const float*)d_in[0];
    const int*   nidx    =(const int*)d_in[1];
    const void*  nmask   =d_in[2];
    const float* conv1w  =(const float*)d_in[3];
    const float* bn1g    =(const float*)d_in[4];
    const float* bn1b    =(const float*)d_in[5];
    const float* conv2w  =(const float*)d_in[6];
    const float* bn2g    =(const float*)d_in[7];
    const float* bn2b    =(const float*)d_in[8];
    float* out=(float*)d_out;

    const int N=in_sizes[0]/CC, nct=N/TM, n4=(N*CC)/4;
    const float invN=1.0f/(float)N;
    const int B=in_sizes[3]/(KK*CC*CC);

    float *pT,*pY,*pX,*pPart; __half *pAh,*pBh; unsigned* pW;
    cudaGetSymbolAddress((void**)&pT,g_T);
    cudaGetSymbolAddress((void**)&pY,g_Y);
    cudaGetSymbolAddress((void**)&pX,g_X);
    cudaGetSymbolAddress((void**)&pPart,g_part);
    cudaGetSymbolAddress((void**)&pAh,g_Ah);
    cudaGetSymbolAddress((void**)&pBh,g_Bh);
    cudaGetSymbolAddress((void**)&pW,g_Wf);

    cudaFuncSetAttribute(conv_kernel,cudaFuncAttributeMaxDynamicSharedMemorySize,SMEM_TOTAL);

    detect_kernel<<<1,1>>>((const unsigned*)nmask);
    {
        const int total=B*2*4608;
        wprep_kernel<<<(total+255)/256,256>>>(conv1w,conv2w,total);
    }
    convert_kernel<<<(n4+255)/256,256>>>(features,pAh,n4);

    const float* xcur=features;
    for(int b=0;b<B;b++){
        conv_kernel<<<148,512,SMEM_TOTAL>>>(pAh,pW+(size_t)(b*2)*WF_LAYER,nidx,nmask,pT,pPart,nct);
        reduce_kernel<<<1,1024>>>(pPart,nct,bn1g+b*CC,bn1b+b*CC,invN);
        bnleaky_kernel<<<(n4+255)/256,256>>>(pT,pBh,n4);

        conv_kernel<<<148,512,SMEM_TOTAL>>>(pBh,pW+(size_t)(b*2+1)*WF_LAYER,nidx,nmask,pY,pPart,nct);
        reduce_kernel<<<1,1024>>>(pPart,nct,bn2g+b*CC,bn2b+b*CC,invN);

        float* dst=(b==B-1)?out:pX;
        bnresleaky_kernel<<<(n4+255)/256,256>>>(pY,xcur,dst,pAh,b<B-1,n4);
        xcur=dst;
    }
}

// round 14
// speedup vs baseline: 1.3386x; 1.0336x over previous
#include <cuda_runtime.h>
#include <cuda_fp16.h>
#include <cstdint>
#include <cstddef>

#define CC 64
#define KK 9
#define TM 128
#define NMAX 131072
#define NTILES (NMAX/TM)
#define LEAK 0.33f

// SMEM: Wf 73728 | A 9x16KB resident 147456 | idx(packed mask) 4608 | Sc 2048
#define SM_WF  0
#define SM_A   73728
#define SM_IDX 221184
#define SM_SC  225792
#define SMEM_TOTAL 227840

// per-layer weight fragment image in u32
#define WF_LAYER 18432

__device__ float g_T[(size_t)NMAX*CC];
__device__ float g_Y[(size_t)NMAX*CC];
__device__ float g_X[(size_t)NMAX*CC];
__device__ __half g_Ah[(size_t)NMAX*CC];
__device__ __half g_Bh[(size_t)NMAX*CC];
__device__ unsigned g_Wf[(size_t)8*WF_LAYER];
__device__ float g_part[(size_t)NTILES*128];
__device__ float g_scale[CC];
__device__ float g_shift[CC];
__device__ int   g_mask_mode;

__device__ __forceinline__ void cpa16(unsigned d,const void* s,int ss){
    asm volatile("cp.async.cg.shared.global [%0], [%1], 16, %2;"::"r"(d),"l"(s),"r"(ss):"memory");
}
#define CP_COMMIT() asm volatile("cp.async.commit_group;":::"memory")
#define CP_WAIT(n)  asm volatile("cp.async.wait_group %0;"::"n"(n):"memory")
#define LDM4(a0,a1,a2,a3,ad) asm volatile( \
    "ldmatrix.sync.aligned.m8n8.x4.shared.b16 {%0,%1,%2,%3}, [%4];" \
    :"=r"(a0),"=r"(a1),"=r"(a2),"=r"(a3):"r"(ad))
#define LDS128(b0,b1,b2,b3,ad) asm volatile( \
    "ld.shared.v4.u32 {%0,%1,%2,%3}, [%4];":"=r"(b0),"=r"(b1),"=r"(b2),"=r"(b3):"r"(ad))
#define MMA(c,A0,A1,A2,A3,B0,B1) asm volatile( \
    "mma.sync.aligned.m16n8k16.row.col.f32.f16.f16.f32 " \
    "{%0,%1,%2,%3},{%4,%5,%6,%7},{%8,%9},{%0,%1,%2,%3};" \
    :"+f"((c)[0]),"+f"((c)[1]),"+f"((c)[2]),"+f"((c)[3]) \
    :"r"(A0),"r"(A1),"r"(A2),"r"(A3),"r"(B0),"r"(B1))

__device__ __forceinline__ unsigned short h2u(__half h){
    union{__half h; unsigned short u;} c; c.h=h; return c.u;
}

__global__ void detect_kernel(const unsigned* __restrict__ m){
    if(threadIdx.x==0&&blockIdx.x==0){
        int f32ok=1; unsigned up=0;
        for(int i=0;i<256;i++){unsigned w=m[i]; if(w!=0u&&w!=0x3F800000u)f32ok=0; up|=(w&0xFFFFFF00u);}
        g_mask_mode = f32ok?2:(up?0:1);
    }
}

// Pack fp32 W[b][k][c][d] into mma B-fragment layout, single fp16 plane.
__global__ void wprep_kernel(const float* __restrict__ w1,const float* __restrict__ w2,int total){
    int i=blockIdx.x*blockDim.x+threadIdx.x; if(i>=total)return;  // (L,k,kc,ntp,lane)
    const int lane=i&31, ntp=(i>>5)&3, kc=(i>>7)&3;
    const int t=i>>9, slice=t%9, L=t/9;
    const int c0=kc*16+(lane&3)*2;
    const float* src=(L&1)?w2:w1;
    const float* S=src+((size_t)(L>>1)*9+slice)*4096;
    unsigned r[4];
    #pragma unroll
    for(int j=0;j<2;j++){
        const int d=(ntp*2+j)*8+(lane>>2);
        __half h0=__float2half_rn(S[c0*64+d]);
        __half h1=__float2half_rn(S[(c0+1)*64+d]);
        __half h2=__float2half_rn(S[(c0+8)*64+d]);
        __half h3=__float2half_rn(S[(c0+9)*64+d]);
        r[2*j]  =((unsigned)h2u(h1)<<16)|h2u(h0);
        r[2*j+1]=((unsigned)h2u(h3)<<16)|h2u(h2);
    }
    *(uint4*)&g_Wf[(size_t)i*4]=make_uint4(r[0],r[1],r[2],r[3]);
}

__global__ void __launch_bounds__(512,1) conv_kernel(
    const __half* __restrict__ xh,
    const unsigned* __restrict__ wf,const int* __restrict__ nidx,
    const void* __restrict__ nmask,float* __restrict__ out,
    float* __restrict__ partials,int ntiles)
{
    extern __shared__ __align__(16) char smem[];
    const unsigned sb=(unsigned)__cvta_generic_to_shared(smem);
    const int tid=threadIdx.x;
    int* idx_s=(int*)(smem+SM_IDX);
    float* Sc =(float*)(smem+SM_SC);   // 512 floats: [sq][rw][c]

    for(int i=tid;i<4608;i+=512)
        cpa16(sb+SM_WF+(unsigned)(i*16), (const char*)wf+(size_t)i*16, 16);
    CP_COMMIT(); CP_WAIT(0);
    __syncthreads();

    // staging: 4 threads per row, chunks 2q,2q+1 of the 128B fp16 row
    const int sr=tid>>2, q=tid&3, rsw=sr&7;
    // compute: warp w -> row group (w&3)*32 (2 m16 tiles), ntp = w>>2
    const int w=tid>>5, lane=tid&31;
    const int rw=w&3, ntg=w>>2;
    const int rowbase=rw<<5;
    const int rq0=rowbase+(lane&15), rq1=rq0+16;
    const unsigned rbs0=(unsigned)(rq0*128), rbs1=(unsigned)(rq1*128);
    const int rx=rq0&7, chsel=lane>>4;

    for(int t=blockIdx.x;t<ntiles;t+=gridDim.x){
        const int tile0=t*TM;
        {
            const int mode=g_mask_mode; const long gb=(long)tile0*KK;
            for(int i=tid;i<TM*KK;i+=512){
                int id=nidx[gb+i];
                int mv;
                if(mode==0)      mv=((const unsigned char*)nmask)[gb+i];
                else if(mode==1) mv=((const int*)nmask)[gb+i]!=0;
                else             mv=((const float*)nmask)[gb+i]!=0.0f;
                idx_s[i]= mv ? id : (id|(int)0x80000000);
            }
        }
        __syncthreads();
        // stage ALL 9 slices (9 commit groups, deep gather MLP)
        #pragma unroll
        for(int p=0;p<KK;p++){
            const int v=idx_s[sr*KK+p];
            const int ss=(v>=0)?16:0;
            const char* s=(const char*)(xh+(size_t)(v&0x7FFFFFFF)*CC);
            const unsigned db=sb+SM_A+(unsigned)(p*16384+sr*128);
            #pragma unroll
            for(int j=0;j<2;j++){
                const int ch=q*2+j;
                cpa16(db+(unsigned)((ch^rsw)<<4), s+ch*16, ss);
            }
            CP_COMMIT();
        }

        float acc[16];   // [rt][nt(2)][4]
        #pragma unroll
        for(int i=0;i<16;i++) acc[i]=0.0f;

        // 3 phases x 3 slices: one wait+barrier per phase
        #pragma unroll
        for(int ph=0;ph<3;ph++){
            if(ph==0)      CP_WAIT(6);
            else if(ph==1) CP_WAIT(3);
            else           CP_WAIT(0);
            __syncthreads();
            #pragma unroll
            for(int kk=0;kk<3;kk++){
                const int k=ph*3+kk;
                const unsigned Ab=sb+SM_A+(unsigned)(k*16384);
                #pragma unroll
                for(int kc=0;kc<4;kc++){
                    const unsigned ch=(unsigned)((kc<<1)+chsel);
                    const unsigned co=(ch^(unsigned)rx)<<4;
                    unsigned a0,a1,a2,a3,a4,a5,a6,a7;
                    LDM4(a0,a1,a2,a3,Ab+rbs0+co);
                    LDM4(a4,a5,a6,a7,Ab+rbs1+co);
                    unsigned b0,b1,b2,b3;
                    LDS128(b0,b1,b2,b3,sb+SM_WF+(unsigned)((((k*4+kc)<<2)+ntg)*512+lane*16));
                    MMA(acc+0, a0,a1,a2,a3,b0,b1);
                    MMA(acc+4, a0,a1,a2,a3,b2,b3);
                    MMA(acc+8, a4,a5,a6,a7,b0,b1);
                    MMA(acc+12,a4,a5,a6,a7,b2,b3);
                }
            }
        }

        // direct-from-register output writes (32B sectors)
        {
            float* og=out+(size_t)tile0*CC;
            #pragma unroll
            for(int rt=0;rt<2;rt++){
                const int row0=rowbase+rt*16+(lane>>2), row1=row0+8;
                #pragma unroll
                for(int j=0;j<2;j++){
                    const int c=ntg*16+j*8+(lane&3)*2;
                    const float* a=acc+rt*8+j*4;
                    *(float2*)(og+(size_t)row0*CC+c)=make_float2(a[0],a[1]);
                    *(float2*)(og+(size_t)row1*CC+c)=make_float2(a[2],a[3]);
                }
            }
        }
        // per-channel BN partials via shuffle reduce
        {
            float s[4], qv[4];
            #pragma unroll
            for(int j=0;j<2;j++)
                #pragma unroll
                for(int b=0;b<2;b++){
                    float a0=acc[0+j*4+b],  a1=acc[0+j*4+2+b];
                    float a2=acc[8+j*4+b],  a3=acc[8+j*4+2+b];
                    s [j*2+b]=a0+a1+a2+a3;
                    qv[j*2+b]=a0*a0+a1*a1+a2*a2+a3*a3;
                }
            #pragma unroll
            for(int m=4;m<32;m<<=1)
                #pragma unroll
                for(int i=0;i<4;i++){
                    s [i]+=__shfl_xor_sync(0xffffffffu,s [i],m);
                    qv[i]+=__shfl_xor_sync(0xffffffffu,qv[i],m);
                }
            if(lane<4){
                #pragma unroll
                for(int i=0;i<4;i++){
                    const int c=ntg*16+(i>>1)*8+lane*2+(i&1);
                    Sc[rw*64+c]    =s [i];
                    Sc[256+rw*64+c]=qv[i];
                }
            }
        }
        __syncthreads();   // Sc ready; also orders all MMA reads before next tile's staging
        if(tid<128){
            const int which=tid>>6, c=tid&63;
            const float* S0=Sc+which*256;
            partials[(size_t)t*128+tid]=S0[c]+S0[64+c]+S0[128+c]+S0[192+c];
        }
    }
}

__global__ void __launch_bounds__(1024) reduce_kernel(
    const float* __restrict__ partials,int nct,
    const float* __restrict__ gamma,const float* __restrict__ beta,float invN)
{
    __shared__ float red[1024];
    const int tid=threadIdx.x;
    const int c=tid&63, which=(tid>>6)&1, part=tid>>7;   // part 0..7
    float a=0.0f;
    for(int cta=part;cta<nct;cta+=8) a+=partials[(size_t)cta*128+which*64+c];
    red[tid]=a; __syncthreads();
    if(tid<512) red[tid]+=red[tid+512];
    __syncthreads();
    if(tid<256) red[tid]+=red[tid+256];
    __syncthreads();
    if(tid<128) red[tid]+=red[tid+128];
    __syncthreads();
    if(tid<64){
        float mean=red[tid]*invN;
        float var=red[tid+64]*invN-mean*mean;
        float sc=gamma[tid]*rsqrtf(var+1e-5f);
        g_scale[tid]=sc; g_shift[tid]=beta[tid]-mean*sc;
    }
}

__device__ __forceinline__ void hstore(__half* hp,size_t i4,float4 z){
    __half2 a=__floats2half2_rn(z.x,z.y);
    __half2 b=__floats2half2_rn(z.z,z.w);
    union{__half2 h[2]; uint2 u;} U; U.h[0]=a; U.h[1]=b;
    *(uint2*)(hp+i4*4)=U.u;
}

__global__ void __launch_bounds__(256) convert_kernel(
    const float* __restrict__ x,__half* hp,int n4){
    int i=blockIdx.x*blockDim.x+threadIdx.x; if(i>=n4)return;
    hstore(hp,(size_t)i,((const float4*)x)[i]);
}

__global__ void __launch_bounds__(256) bnleaky_kernel(
    const float* __restrict__ t,__half* hp,int n4){
    int i=blockIdx.x*blockDim.x+threadIdx.x; if(i>=n4)return;
    const int c=(i<<2)&63;
    const float4 sc=*(const float4*)(g_scale+c), sh=*(const float4*)(g_shift+c);
    float4 v=((const float4*)t)[i]; float x;
    x=v.x*sc.x+sh.x; v.x=x>0?x:LEAK*x;
    x=v.y*sc.y+sh.y; v.y=x>0?x:LEAK*x;
    x=v.z*sc.z+sh.z; v.z=x>0?x:LEAK*x;
    x=v.w*sc.w+sh.w; v.w=x>0?x:LEAK*x;
    hstore(hp,(size_t)i,v);
}

__global__ void __launch_bounds__(256) bnresleaky_kernel(
    const float* __restrict__ y,const float* __restrict__ res,float* __restrict__ op,
    __half* hp,int wp,int n4){
    int i=blockIdx.x*blockDim.x+threadIdx.x; if(i>=n4)return;
    const int c=(i<<2)&63;
    const float4 sc=*(const float4*)(g_scale+c), sh=*(const float4*)(g_shift+c);
    float4 v=((const float4*)y)[i]; const float4 r=((const float4*)res)[i]; float x;
    x=v.x*sc.x+sh.x+r.x; v.x=x>0?x:LEAK*x;
    x=v.y*sc.y+sh.y+r.y; v.y=x>0?x:LEAK*x;
    x=v.z*sc.z+sh.z+r.z; v.z=x>0?x:LEAK*x;
    x=v.w*sc.w+sh.w+r.w; v.w=x>0?x:LEAK*x;
    ((float4*)op)[i]=v;
    if(wp) hstore(hp,(size_t)i,v);
}

extern "C" void kernel_launch(void* const* d_in,const int* in_sizes,int n_in,
                              void* d_out,int out_size)
{
    const float* features=(const float*)d_in[0];
    const int*   nidx    =(const int*)d_in[1];
    const void*  nmask   =d_in[2];
    const float* conv1w  =(const float*)d_in[3];
    const float* bn1g    =(const float*)d_in[4];
    const float* bn1b    =(const float*)d_in[5];
    const float* conv2w  =(const float*)d_in[6];
    const float* bn2g    =(const float*)d_in[7];
    const float* bn2b    =(const float*)d_in[8];
    float* out=(float*)d_out;

    const int N=in_sizes[0]/CC, nct=N/TM, n4=(N*CC)/4;
    const float invN=1.0f/(float)N;
    const int B=in_sizes[3]/(KK*CC*CC);

    float *pT,*pY,*pX,*pPart; __half *pAh,*pBh; unsigned* pW;
    cudaGetSymbolAddress((void**)&pT,g_T);
    cudaGetSymbolAddress((void**)&pY,g_Y);
    cudaGetSymbolAddress((void**)&pX,g_X);
    cudaGetSymbolAddress((void**)&pPart,g_part);
    cudaGetSymbolAddress((void**)&pAh,g_Ah);
    cudaGetSymbolAddress((void**)&pBh,g_Bh);
    cudaGetSymbolAddress((void**)&pW,g_Wf);

    cudaFuncSetAttribute(conv_kernel,cudaFuncAttributeMaxDynamicSharedMemorySize,SMEM_TOTAL);

    detect_kernel<<<1,1>>>((const unsigned*)nmask);
    {
        const int total=B*2*4608;
        wprep_kernel<<<(total+255)/256,256>>>(conv1w,conv2w,total);
    }
    convert_kernel<<<(n4+255)/256,256>>>(features,pAh,n4);

    const float* xcur=features;
    for(int b=0;b<B;b++){
        conv_kernel<<<148,512,SMEM_TOTAL>>>(pAh,pW+(size_t)(b*2)*WF_LAYER,nidx,nmask,pT,pPart,nct);
        reduce_kernel<<<1,1024>>>(pPart,nct,bn1g+b*CC,bn1b+b*CC,invN);
        bnleaky_kernel<<<(n4+255)/256,256>>>(pT,pBh,n4);

        conv_kernel<<<148,512,SMEM_TOTAL>>>(pBh,pW+(size_t)(b*2+1)*WF_LAYER,nidx,nmask,pY,pPart,nct);
        reduce_kernel<<<1,1024>>>(pPart,nct,bn2g+b*CC,bn2b+b*CC,invN);

        float* dst=(b==B-1)?out:pX;
        bnresleaky_kernel<<<(n4+255)/256,256>>>(pY,xcur,dst,pAh,b<B-1,n4);
        xcur=dst;
    }
}

// round 15
// speedup vs baseline: 1.4095x; 1.0529x over previous
#include <cuda_runtime.h>
#include <cuda_fp16.h>
#include <cstdint>
#include <cstddef>

#define CC 64
#define KK 9
#define TM 128
#define NMAX 131072
#define NTILES (NMAX/TM)
#define LEAK 0.33f

// SMEM: Wf 73728 | A 9x16KB resident 147456 | idx(packed mask) 4608 | Sc 2048
#define SM_WF  0
#define SM_A   73728
#define SM_IDX 221184
#define SM_SC  225792
#define SMEM_TOTAL 227840

#define WF_LAYER 18432

__device__ float g_X[(size_t)NMAX*CC];
__device__ __half g_Th[(size_t)NMAX*CC];   // conv1 output (fp16)
__device__ __half g_Yh[(size_t)NMAX*CC];   // conv2 output (fp16)
__device__ __half g_Ah[(size_t)NMAX*CC];
__device__ __half g_Bh[(size_t)NMAX*CC];
__device__ unsigned g_Wf[(size_t)8*WF_LAYER];
__device__ float g_part[(size_t)NTILES*128];
__device__ float g_scale[CC];
__device__ float g_shift[CC];
__device__ int   g_mask_mode;

__device__ __forceinline__ void cpa16(unsigned d,const void* s,int ss){
    asm volatile("cp.async.cg.shared.global [%0], [%1], 16, %2;"::"r"(d),"l"(s),"r"(ss):"memory");
}
#define CP_COMMIT() asm volatile("cp.async.commit_group;":::"memory")
#define CP_WAIT(n)  asm volatile("cp.async.wait_group %0;"::"n"(n):"memory")
#define LDM4(a0,a1,a2,a3,ad) asm volatile( \
    "ldmatrix.sync.aligned.m8n8.x4.shared.b16 {%0,%1,%2,%3}, [%4];" \
    :"=r"(a0),"=r"(a1),"=r"(a2),"=r"(a3):"r"(ad))
#define LDS128(b0,b1,b2,b3,ad) asm volatile( \
    "ld.shared.v4.u32 {%0,%1,%2,%3}, [%4];":"=r"(b0),"=r"(b1),"=r"(b2),"=r"(b3):"r"(ad))
#define MMA(c,A0,A1,A2,A3,B0,B1) asm volatile( \
    "mma.sync.aligned.m16n8k16.row.col.f32.f16.f16.f32 " \
    "{%0,%1,%2,%3},{%4,%5,%6,%7},{%8,%9},{%0,%1,%2,%3};" \
    :"+f"((c)[0]),"+f"((c)[1]),"+f"((c)[2]),"+f"((c)[3]) \
    :"r"(A0),"r"(A1),"r"(A2),"r"(A3),"r"(B0),"r"(B1))

__device__ __forceinline__ unsigned short h2u(__half h){
    union{__half h; unsigned short u;} c; c.h=h; return c.u;
}

__global__ void detect_kernel(const unsigned* __restrict__ m){
    if(threadIdx.x==0&&blockIdx.x==0){
        int f32ok=1; unsigned up=0;
        for(int i=0;i<256;i++){unsigned w=m[i]; if(w!=0u&&w!=0x3F800000u)f32ok=0; up|=(w&0xFFFFFF00u);}
        g_mask_mode = f32ok?2:(up?0:1);
    }
}

// Pack fp32 W[b][k][c][d] into mma B-fragment layout, single fp16 plane.
__global__ void wprep_kernel(const float* __restrict__ w1,const float* __restrict__ w2,int total){
    int i=blockIdx.x*blockDim.x+threadIdx.x; if(i>=total)return;  // (L,k,kc,ntp,lane)
    const int lane=i&31, ntp=(i>>5)&3, kc=(i>>7)&3;
    const int t=i>>9, slice=t%9, L=t/9;
    const int c0=kc*16+(lane&3)*2;
    const float* src=(L&1)?w2:w1;
    const float* S=src+((size_t)(L>>1)*9+slice)*4096;
    unsigned r[4];
    #pragma unroll
    for(int j=0;j<2;j++){
        const int d=(ntp*2+j)*8+(lane>>2);
        __half h0=__float2half_rn(S[c0*64+d]);
        __half h1=__float2half_rn(S[(c0+1)*64+d]);
        __half h2=__float2half_rn(S[(c0+8)*64+d]);
        __half h3=__float2half_rn(S[(c0+9)*64+d]);
        r[2*j]  =((unsigned)h2u(h1)<<16)|h2u(h0);
        r[2*j+1]=((unsigned)h2u(h3)<<16)|h2u(h2);
    }
    *(uint4*)&g_Wf[(size_t)i*4]=make_uint4(r[0],r[1],r[2],r[3]);
}

__global__ void __launch_bounds__(512,1) conv_kernel(
    const __half* __restrict__ xh,
    const unsigned* __restrict__ wf,const int* __restrict__ nidx,
    const void* __restrict__ nmask,__half* __restrict__ out,
    float* __restrict__ partials,int ntiles)
{
    extern __shared__ __align__(16) char smem[];
    const unsigned sb=(unsigned)__cvta_generic_to_shared(smem);
    const int tid=threadIdx.x;
    int* idx_s=(int*)(smem+SM_IDX);
    float* Sc =(float*)(smem+SM_SC);

    for(int i=tid;i<4608;i+=512)
        cpa16(sb+SM_WF+(unsigned)(i*16), (const char*)wf+(size_t)i*16, 16);
    CP_COMMIT(); CP_WAIT(0);
    __syncthreads();

    const int sr=tid>>2, q=tid&3, rsw=sr&7;
    const int w=tid>>5, lane=tid&31;
    const int rw=w&3, ntg=w>>2;
    const int rowbase=rw<<5;
    const int rq0=rowbase+(lane&15), rq1=rq0+16;
    const unsigned rbs0=(unsigned)(rq0*128), rbs1=(unsigned)(rq1*128);
    const int rx=rq0&7, chsel=lane>>4;

    for(int t=blockIdx.x;t<ntiles;t+=gridDim.x){
        const int tile0=t*TM;
        {
            const int mode=g_mask_mode; const long gb=(long)tile0*KK;
            for(int i=tid;i<TM*KK;i+=512){
                int id=nidx[gb+i];
                int mv;
                if(mode==0)      mv=((const unsigned char*)nmask)[gb+i];
                else if(mode==1) mv=((const int*)nmask)[gb+i]!=0;
                else             mv=((const float*)nmask)[gb+i]!=0.0f;
                idx_s[i]= mv ? id : (id|(int)0x80000000);
            }
        }
        __syncthreads();
        #pragma unroll
        for(int p=0;p<KK;p++){
            const int v=idx_s[sr*KK+p];
            const int ss=(v>=0)?16:0;
            const char* s=(const char*)(xh+(size_t)(v&0x7FFFFFFF)*CC);
            const unsigned db=sb+SM_A+(unsigned)(p*16384+sr*128);
            #pragma unroll
            for(int j=0;j<2;j++){
                const int ch=q*2+j;
                cpa16(db+(unsigned)((ch^rsw)<<4), s+ch*16, ss);
            }
            CP_COMMIT();
        }

        float acc[16];
        #pragma unroll
        for(int i=0;i<16;i++) acc[i]=0.0f;

        #pragma unroll
        for(int ph=0;ph<3;ph++){
            if(ph==0)      CP_WAIT(6);
            else if(ph==1) CP_WAIT(3);
            else           CP_WAIT(0);
            __syncthreads();
            #pragma unroll
            for(int kk=0;kk<3;kk++){
                const int k=ph*3+kk;
                const unsigned Ab=sb+SM_A+(unsigned)(k*16384);
                #pragma unroll
                for(int kc=0;kc<4;kc++){
                    const unsigned ch=(unsigned)((kc<<1)+chsel);
                    const unsigned co=(ch^(unsigned)rx)<<4;
                    unsigned a0,a1,a2,a3,a4,a5,a6,a7;
                    LDM4(a0,a1,a2,a3,Ab+rbs0+co);
                    LDM4(a4,a5,a6,a7,Ab+rbs1+co);
                    unsigned b0,b1,b2,b3;
                    LDS128(b0,b1,b2,b3,sb+SM_WF+(unsigned)((((k*4+kc)<<2)+ntg)*512+lane*16));
                    MMA(acc+0, a0,a1,a2,a3,b0,b1);
                    MMA(acc+4, a0,a1,a2,a3,b2,b3);
                    MMA(acc+8, a4,a5,a6,a7,b0,b1);
                    MMA(acc+12,a4,a5,a6,a7,b2,b3);
                }
            }
        }

        // direct-from-register fp16 output writes
        {
            __half* og=out+(size_t)tile0*CC;
            #pragma unroll
            for(int rt=0;rt<2;rt++){
                const int row0=rowbase+rt*16+(lane>>2), row1=row0+8;
                #pragma unroll
                for(int j=0;j<2;j++){
                    const int c=ntg*16+j*8+(lane&3)*2;
                    const float* a=acc+rt*8+j*4;
                    *(__half2*)(og+(size_t)row0*CC+c)=__floats2half2_rn(a[0],a[1]);
                    *(__half2*)(og+(size_t)row1*CC+c)=__floats2half2_rn(a[2],a[3]);
                }
            }
        }
        // per-channel BN partials via shuffle reduce (full-precision accs)
        {
            float s[4], qv[4];
            #pragma unroll
            for(int j=0;j<2;j++)
                #pragma unroll
                for(int b=0;b<2;b++){
                    float a0=acc[0+j*4+b],  a1=acc[0+j*4+2+b];
                    float a2=acc[8+j*4+b],  a3=acc[8+j*4+2+b];
                    s [j*2+b]=a0+a1+a2+a3;
                    qv[j*2+b]=a0*a0+a1*a1+a2*a2+a3*a3;
                }
            #pragma unroll
            for(int m=4;m<32;m<<=1)
                #pragma unroll
                for(int i=0;i<4;i++){
                    s [i]+=__shfl_xor_sync(0xffffffffu,s [i],m);
                    qv[i]+=__shfl_xor_sync(0xffffffffu,qv[i],m);
                }
            if(lane<4){
                #pragma unroll
                for(int i=0;i<4;i++){
                    const int c=ntg*16+(i>>1)*8+lane*2+(i&1);
                    Sc[rw*64+c]    =s [i];
                    Sc[256+rw*64+c]=qv[i];
                }
            }
        }
        __syncthreads();
        if(tid<128){
            const int which=tid>>6, c=tid&63;
            const float* S0=Sc+which*256;
            partials[(size_t)t*128+tid]=S0[c]+S0[64+c]+S0[128+c]+S0[192+c];
        }
    }
}

__global__ void __launch_bounds__(1024) reduce_kernel(
    const float* __restrict__ partials,int nct,
    const float* __restrict__ gamma,const float* __restrict__ beta,float invN)
{
    __shared__ float red[1024];
    const int tid=threadIdx.x;
    const int c=tid&63, which=(tid>>6)&1, part=tid>>7;
    float a=0.0f;
    for(int cta=part;cta<nct;cta+=8) a+=partials[(size_t)cta*128+which*64+c];
    red[tid]=a; __syncthreads();
    if(tid<512) red[tid]+=red[tid+512];
    __syncthreads();
    if(tid<256) red[tid]+=red[tid+256];
    __syncthreads();
    if(tid<128) red[tid]+=red[tid+128];
    __syncthreads();
    if(tid<64){
        float mean=red[tid]*invN;
        float var=red[tid+64]*invN-mean*mean;
        float sc=gamma[tid]*rsqrtf(var+1e-5f);
        g_scale[tid]=sc; g_shift[tid]=beta[tid]-mean*sc;
    }
}

__device__ __forceinline__ void hstore(__half* hp,size_t i4,float4 z){
    __half2 a=__floats2half2_rn(z.x,z.y);
    __half2 b=__floats2half2_rn(z.z,z.w);
    union{__half2 h[2]; uint2 u;} U; U.h[0]=a; U.h[1]=b;
    *(uint2*)(hp+i4*4)=U.u;
}
__device__ __forceinline__ float4 hload4(const __half* hp,size_t i4){
    uint2 u=*(const uint2*)(hp+i4*4);
    union{unsigned u; __half2 h;} A,B; A.u=u.x; B.u=u.y;
    float2 a=__half22float2(A.h), b=__half22float2(B.h);
    return make_float4(a.x,a.y,b.x,b.y);
}

__global__ void __launch_bounds__(256) convert_kernel(
    const float* __restrict__ x,__half* hp,int n4){
    int i=blockIdx.x*blockDim.x+threadIdx.x; if(i>=n4)return;
    hstore(hp,(size_t)i,((const float4*)x)[i]);
}

__global__ void __launch_bounds__(256) bnleaky_kernel(
    const __half* __restrict__ t,__half* hp,int n4){
    int i=blockIdx.x*blockDim.x+threadIdx.x; if(i>=n4)return;
    const int c=(i<<2)&63;
    const float4 sc=*(const float4*)(g_scale+c), sh=*(const float4*)(g_shift+c);
    float4 v=hload4(t,(size_t)i); float x;
    x=v.x*sc.x+sh.x; v.x=x>0?x:LEAK*x;
    x=v.y*sc.y+sh.y; v.y=x>0?x:LEAK*x;
    x=v.z*sc.z+sh.z; v.z=x>0?x:LEAK*x;
    x=v.w*sc.w+sh.w; v.w=x>0?x:LEAK*x;
    hstore(hp,(size_t)i,v);
}

__global__ void __launch_bounds__(256) bnresleaky_kernel(
    const __half* __restrict__ y,const float* __restrict__ res,float* __restrict__ op,
    __half* hp,int wp,int n4){
    int i=blockIdx.x*blockDim.x+threadIdx.x; if(i>=n4)return;
    const int c=(i<<2)&63;
    const float4 sc=*(const float4*)(g_scale+c), sh=*(const float4*)(g_shift+c);
    float4 v=hload4(y,(size_t)i); const float4 r=((const float4*)res)[i]; float x;
    x=v.x*sc.x+sh.x+r.x; v.x=x>0?x:LEAK*x;
    x=v.y*sc.y+sh.y+r.y; v.y=x>0?x:LEAK*x;
    x=v.z*sc.z+sh.z+r.z; v.z=x>0?x:LEAK*x;
    x=v.w*sc.w+sh.w+r.w; v.w=x>0?x:LEAK*x;
    ((float4*)op)[i]=v;
    if(wp) hstore(hp,(size_t)i,v);
}

extern "C" void kernel_launch(void* const* d_in,const int* in_sizes,int n_in,
                              void* d_out,int out_size)
{
    const float* features=(const float*)d_in[0];
    const int*   nidx    =(const int*)d_in[1];
    const void*  nmask   =d_in[2];
    const float* conv1w  =(const float*)d_in[3];
    const float* bn1g    =(const float*)d_in[4];
    const float* bn1b    =(const float*)d_in[5];
    const float* conv2w  =(const float*)d_in[6];
    const float* bn2g    =(const float*)d_in[7];
    const float* bn2b    =(const float*)d_in[8];
    float* out=(float*)d_out;

    const int N=in_sizes[0]/CC, nct=N/TM, n4=(N*CC)/4;
    const float invN=1.0f/(float)N;
    const int B=in_sizes[3]/(KK*CC*CC);

    float *pX,*pPart; __half *pAh,*pBh,*pTh,*pYh; unsigned* pW;
    cudaGetSymbolAddress((void**)&pX,g_X);
    cudaGetSymbolAddress((void**)&pPart,g_part);
    cudaGetSymbolAddress((void**)&pAh,g_Ah);
    cudaGetSymbolAddress((void**)&pBh,g_Bh);
    cudaGetSymbolAddress((void**)&pTh,g_Th);
    cudaGetSymbolAddress((void**)&pYh,g_Yh);
    cudaGetSymbolAddress((void**)&pW,g_Wf);

    cudaFuncSetAttribute(conv_kernel,cudaFuncAttributeMaxDynamicSharedMemorySize,SMEM_TOTAL);

    detect_kernel<<<1,1>>>((const unsigned*)nmask);
    {
        const int total=B*2*4608;
        wprep_kernel<<<(total+255)/256,256>>>(conv1w,conv2w,total);
    }
    convert_kernel<<<(n4+255)/256,256>>>(features,pAh,n4);

    const float* xcur=features;
    for(int b=0;b<B;b++){
        conv_kernel<<<148,512,SMEM_TOTAL>>>(pAh,pW+(size_t)(b*2)*WF_LAYER,nidx,nmask,pTh,pPart,nct);
        reduce_kernel<<<1,1024>>>(pPart,nct,bn1g+b*CC,bn1b+b*CC,invN);
        bnleaky_kernel<<<(n4+255)/256,256>>>(pTh,pBh,n4);

        conv_kernel<<<148,512,SMEM_TOTAL>>>(pBh,pW+(size_t)(b*2+1)*WF_LAYER,nidx,nmask,pYh,pPart,nct);
        reduce_kernel<<<1,1024>>>(pPart,nct,bn2g+b*CC,bn2b+b*CC,invN);

        float* dst=(b==B-1)?out:pX;
        bnresleaky_kernel<<<(n4+255)/256,256>>>(pYh,xcur,dst,pAh,b<B-1,n4);
        xcur=dst;
    }
}